// round 15
// baseline (speedup 1.0000x reference)
#include <cuda_runtime.h>
#include <cstdint>

#define BS 16
#define A  33600
#define G  64
#define C  80
#define EPSF 1e-7f
#define CAP 4096

#define TILE 256
#define NCHUNK ((A + TILE - 1) / TILE)

#define INV_PI2_4 0.4052847345693511f

// Scratch (device globals — no runtime allocation allowed)
__device__ unsigned long long g_key[(size_t)BS * G * CAP]; // candidate (fkey(cost)<<32 | a)
__device__ int                g_cnt[BS * G];               // candidate counts
__device__ float              g_iov[(size_t)BS * G * CAP]; // positive iouv values per (b,g)
__device__ int                g_icnt[BS * G];              // value list counts
__device__ float4             g_fpb  [(size_t)BS * A];     // filt anchors: pred box
__device__ int                g_fa   [(size_t)BS * A];     // filt anchors: anchor index
__device__ unsigned long long g_fmask[(size_t)BS * A];     // filt anchors: ic mask
__device__ int                g_fcnt[BS];                  // filt counts
__device__ unsigned char      g_filt[(size_t)BS * A];      // per-anchor anchor_filter
__device__ unsigned long long g_amin[(size_t)BS * A];      // per-anchor argmin (fkey<<6|g)
__device__ int                g_mcnt[(size_t)BS * A];      // match count per anchor
__device__ int                g_mfg [(size_t)BS * A];      // min matched g per anchor

// Monotone float -> uint32 order-preserving transform
__device__ __forceinline__ unsigned int fkey(float f) {
    unsigned int b = __float_as_uint(f);
    return b ^ ((unsigned int)((int)b >> 31) | 0x80000000u);
}

// ---------------------------------------------------------------------------
// KZ: zero small counters (single block)
// ---------------------------------------------------------------------------
__global__ void kz() {
    int i = threadIdx.x;
    if (i < BS * G) { g_cnt[i] = 0; g_icnt[i] = 0; }
    if (i < BS)     g_fcnt[i] = 0;
}

// ---------------------------------------------------------------------------
// K1a: per (b,a): in-center mask + compaction of filt anchors into per-batch
// lists; also zero-inits per-anchor match state.
// ---------------------------------------------------------------------------
__global__ __launch_bounds__(TILE) void k1a(
    const float* __restrict__ pboxes, const float* __restrict__ anc,
    const float* __restrict__ gbox,   const int*   __restrict__ gmask,
    const float* __restrict__ strd)
{
    __shared__ float2 s_gc[G];
    __shared__ unsigned int s_vm[2];

    const int tid = threadIdx.x;
    const int b   = blockIdx.y;

    if (tid < G) {
        const float* gb = gbox + ((size_t)b * G + tid) * 4;
        s_gc[tid] = make_float2((gb[0] + gb[2]) * 0.5f, (gb[1] + gb[3]) * 0.5f);
        unsigned int bal = __ballot_sync(0xFFFFFFFFu, gmask[b * G + tid] != 0);
        if ((tid & 31) == 0) s_vm[tid >> 5] = bal;
    }
    __syncthreads();

    const int a = blockIdx.x * TILE + tid;
    if (a >= A) return;   // warp-uniform (A % 32 == 0)

    const size_t ba = (size_t)b * A + a;
    g_mcnt[ba] = 0;
    g_mfg [ba] = 0x7FFFFFFF;
    g_amin[ba] = 0xFFFFFFFFFFFFFFFFull;

    const unsigned long long vmask =
        (unsigned long long)s_vm[0] | ((unsigned long long)s_vm[1] << 32);

    const float ax = anc[a * 2 + 0], ay = anc[a * 2 + 1];
    const float cd = strd[ba] * 2.5f;

    unsigned long long mask = 0ull;
    #pragma unroll
    for (int g = 0; g < G; g++) {
        float2 gc = s_gc[g];
        bool ic = (fabsf(ax - gc.x) < cd) && (fabsf(ay - gc.y) < cd);
        mask |= ((unsigned long long)ic) << g;
    }
    mask &= vmask;
    const bool filt = (mask != 0ull);
    g_filt[ba] = filt ? 1 : 0;

    unsigned int fm = __ballot_sync(0xFFFFFFFFu, filt);
    if (filt) {
        const float4 pb = *(const float4*)(pboxes + ba * 4);
        int lane   = tid & 31;
        int leader = __ffs(fm) - 1;
        int basei = 0;
        if (lane == leader) basei = atomicAdd(&g_fcnt[b], __popc(fm));
        basei = __shfl_sync(fm, basei, leader);
        int slot = basei + __popc(fm & ((1u << lane) - 1u));
        size_t off = (size_t)b * A + slot;
        g_fpb  [off] = pb;
        g_fa   [off] = a;
        g_fmask[off] = mask;
    }
}

// ---------------------------------------------------------------------------
// K1b: dense pass over the compacted filt-anchor list.
// Branch-free intersect|ic bitmask, then while over SET BITS only.
// One CIoU per set bit; positive iouv -> per-(b,g) value list; ic bits emit
// cost key + argmin.
// ---------------------------------------------------------------------------
__global__ __launch_bounds__(TILE) void k1b(
    const float* __restrict__ scores, const int* __restrict__ glab,
    const float* __restrict__ gbox,   const int* __restrict__ gmask)
{
    __shared__ float4 s_box[G];
    __shared__ float4 s_aux[G];   // sx, sy, w1h1, at1
    __shared__ int    s_lab[G];
    __shared__ unsigned int s_vm[2];

    const int tid = threadIdx.x;
    const int b   = blockIdx.y;

    if (tid < G) {
        const float* gb = gbox + ((size_t)b * G + tid) * 4;
        float x1 = gb[0], y1 = gb[1], x2 = gb[2], y2 = gb[3];
        s_box[tid] = make_float4(x1, y1, x2, y2);
        float w1 = x2 - x1, h1 = y2 - y1;
        s_aux[tid] = make_float4(x1 + x2, y1 + y2, w1 * h1, atanf(__fdividef(w1, h1 + EPSF)));
        s_lab[tid] = glab[b * G + tid];
        unsigned int bal = __ballot_sync(0xFFFFFFFFu, gmask[b * G + tid] != 0);
        if ((tid & 31) == 0) s_vm[tid >> 5] = bal;
    }
    __syncthreads();

    const int i = blockIdx.x * TILE + tid;
    if (i >= g_fcnt[b]) return;

    const unsigned long long vmask =
        (unsigned long long)s_vm[0] | ((unsigned long long)s_vm[1] << 32);

    const size_t off = (size_t)b * A + i;
    const int a = g_fa[off];
    const float4 pb = g_fpb[off];
    const float w2 = pb.z - pb.x, h2 = pb.w - pb.y;
    const float w2h2 = w2 * h2;
    const float at2  = atanf(__fdividef(w2, h2 + EPSF));
    const unsigned long long mask = g_fmask[off];   // ic & vmask
    const float psx = pb.x + pb.z, psy = pb.y + pb.w;

    const size_t ba = (size_t)b * A + a;
    const float* srow = scores + ba * C;

    // base = sum_c -log1p(-sqrt(s_c))
    float base = 0.0f;
    const float4* srow4 = (const float4*)srow;
    #pragma unroll
    for (int q = 0; q < C / 4; q++) {
        float4 v = srow4[q];
        float ss[4] = {v.x, v.y, v.z, v.w};
        #pragma unroll
        for (int j = 0; j < 4; j++) {
            float p = __fsqrt_rn(ss[j]);
            base -= fmaxf(__logf(1.0f - p), -100.0f);
        }
    }

    // Branch-free intersect mask
    unsigned long long im = 0ull;
    #pragma unroll 8
    for (int g = 0; g < G; g++) {
        const float4 bx = s_box[g];
        bool ix = (fminf(bx.z, pb.z) > fmaxf(bx.x, pb.x)) &&
                  (fminf(bx.w, pb.w) > fmaxf(bx.y, pb.y));
        im |= ((unsigned long long)ix) << g;
    }
    im = (im & vmask) | mask;

    unsigned long long amin = 0xFFFFFFFFFFFFFFFFull;
    unsigned long long mm = im;
    while (mm) {
        int g = __ffsll((long long)mm) - 1;
        mm &= mm - 1;
        const float4 bx = s_box[g];
        const float4 au = s_aux[g];
        float iw = fmaxf(fminf(bx.z, pb.z) - fmaxf(bx.x, pb.x), 0.0f);
        float ih = fmaxf(fminf(bx.w, pb.w) - fmaxf(bx.y, pb.y), 0.0f);
        float inter = iw * ih;
        float uni   = au.z + w2h2 - inter + EPSF;
        float iou   = __fdividef(inter, uni);
        float cw    = fmaxf(bx.z, pb.z) - fminf(bx.x, pb.x);
        float ch    = fmaxf(bx.w, pb.w) - fminf(bx.y, pb.y);
        float c2    = cw * cw + ch * ch + EPSF;
        float dx    = psx - au.x, dy = psy - au.y;
        float rho2  = (dx * dx + dy * dy) * 0.25f;
        float da    = at2 - au.w;
        float v     = INV_PI2_4 * da * da;
        float alpha = __fdividef(v, v - iou + (1.0f + EPSF));
        float ciou  = iou - (__fdividef(rho2, c2) + v * alpha);
        float iouv  = fmaxf(ciou, 0.0f);

        if (iouv > 0.0f) {
            int slot = atomicAdd(&g_icnt[b * G + g], 1);
            if (slot < CAP) g_iov[(size_t)(b * G + g) * CAP + slot] = iouv;
        }

        if ((mask >> g) & 1ull) {
            float s   = srow[s_lab[g]];
            float p   = __fsqrt_rn(s);
            float lp  = fmaxf(0.5f * __logf(s), -100.0f);
            float l1m = fmaxf(__logf(1.0f - p), -100.0f);
            float cost = base + (l1m - lp) - 3.0f * __logf(iouv + 1e-8f);

            unsigned int k32 = fkey(cost);
            unsigned long long pk = (((unsigned long long)k32) << 6) | (unsigned int)g;
            if (pk < amin) amin = pk;

            int slot = atomicAdd(&g_cnt[b * G + g], 1);
            if (slot < CAP)
                g_key[(size_t)(b * G + g) * CAP + slot] =
                    (((unsigned long long)k32) << 32) | (unsigned int)a;
        }
    }
    g_amin[ba] = amin;
}

// ---------------------------------------------------------------------------
// K2: 256-thread block per (b,g). Phase A: parallel value-list scan ->
// merge tree -> dyn_k. Phase B: parallel key-list scan -> merge tree ->
// T = bot[dynk-1] (static compare) -> parallel marking. No serial
// extraction loops; trees alias one 20KB smem buffer.
// ---------------------------------------------------------------------------
__global__ __launch_bounds__(256, 6) void k2(
    const float* __restrict__ scores, const float* __restrict__ pboxes,
    const int* __restrict__ glab, const float* __restrict__ gbox,
    const int* __restrict__ gmask)
{
    __shared__ unsigned long long kc[10 * 256];   // aliased as float for tree A
    __shared__ int s_dynk;
    __shared__ unsigned long long s_T;
    float* fc = (float*)kc;

    const int bg  = blockIdx.x;
    const int tid = threadIdx.x;
    const int b = bg >> 6, g = bg & 63;
    if (gmask[bg] == 0) return;

    // ---- Phase A: top-10 of iou values -> dyn_k ----
    const int n_i = min(g_icnt[bg], CAP);
    const float* vl = g_iov + (size_t)bg * CAP;
    float top[10];
    #pragma unroll
    for (int j = 0; j < 10; j++) top[j] = 0.0f;
    for (int i = tid; i < n_i; i += 256) {
        float v = vl[i];
        if (v > top[9]) {
            top[9] = v;
            #pragma unroll
            for (int j = 8; j >= 0; j--)
                if (top[j + 1] > top[j]) { float t = top[j]; top[j] = top[j + 1]; top[j + 1] = t; }
        }
    }
    #pragma unroll
    for (int j = 0; j < 10; j++) fc[j * 256 + tid] = top[j];
    __syncthreads();

    for (int s = 128; s >= 1; s >>= 1) {
        if (tid < s) {
            #pragma unroll
            for (int j = 0; j < 10; j++) {
                float v = fc[j * 256 + tid + s];
                if (v > top[9]) {
                    top[9] = v;
                    #pragma unroll
                    for (int t = 8; t >= 0; t--)
                        if (top[t + 1] > top[t]) { float tt = top[t]; top[t] = top[t + 1]; top[t + 1] = tt; }
                }
            }
            #pragma unroll
            for (int j = 0; j < 10; j++) fc[j * 256 + tid] = top[j];
        }
        __syncthreads();
    }
    if (tid == 0) {
        float sum = 0.0f;
        #pragma unroll
        for (int j = 0; j < 10; j++) sum += top[j];   // descending = top_k sum order
        s_dynk = max((int)(sum + 0.5f), 1);
    }
    __syncthreads();
    const int dynk = s_dynk;   // <= 10

    // ---- Phase B: bot-10 of cost keys -> T = dynk-th smallest; mark ----
    const int n = min(g_cnt[bg], CAP);
    const unsigned long long* kl = g_key + (size_t)bg * CAP;

    if (n > 0) {
        unsigned long long bot[10];
        #pragma unroll
        for (int j = 0; j < 10; j++) bot[j] = 0xFFFFFFFFFFFFFFFFull;
        for (int i = tid; i < n; i += 256) {
            unsigned long long key = kl[i];
            if (key < bot[9]) {
                bot[9] = key;
                #pragma unroll
                for (int j = 8; j >= 0; j--)
                    if (bot[j + 1] < bot[j]) { unsigned long long t = bot[j]; bot[j] = bot[j + 1]; bot[j + 1] = t; }
            }
        }
        #pragma unroll
        for (int j = 0; j < 10; j++) kc[j * 256 + tid] = bot[j];
        __syncthreads();

        for (int s = 128; s >= 1; s >>= 1) {
            if (tid < s) {
                #pragma unroll
                for (int j = 0; j < 10; j++) {
                    unsigned long long v = kc[j * 256 + tid + s];
                    if (v < bot[9]) {
                        bot[9] = v;
                        #pragma unroll
                        for (int t = 8; t >= 0; t--)
                            if (bot[t + 1] < bot[t]) { unsigned long long tt = bot[t]; bot[t] = bot[t + 1]; bot[t + 1] = tt; }
                    }
                }
                #pragma unroll
                for (int j = 0; j < 10; j++) kc[j * 256 + tid] = bot[j];
            }
            __syncthreads();
        }
        if (tid == 0) {
            unsigned long long T = 0xFFFFFFFFFFFFFFFFull;
            #pragma unroll
            for (int j = 0; j < 10; j++)      // static compare, no dynamic indexing
                if (j == dynk - 1) T = bot[j];
            s_T = T;
        }
        __syncthreads();
        const unsigned long long T = s_T;

        for (int i = tid; i < n; i += 256) {
            unsigned long long key = kl[i];
            if (key <= T) {
                unsigned int aa = (unsigned int)key;
                atomicAdd(&g_mcnt[(size_t)b * A + aa], 1);
                atomicMin(&g_mfg [(size_t)b * A + aa], g);
            }
        }
    } else {
        // Fallback (statistically unreachable): warp 0 global row min.
        if (tid >= 32) return;
        const int lane = tid;
        const float* gb = gbox + (size_t)bg * 4;
        const float x1 = gb[0], y1 = gb[1], x2 = gb[2], y2 = gb[3];
        const float w1 = x2 - x1, h1 = y2 - y1, w1h1 = w1 * h1;
        const float at1 = atanf(__fdividef(w1, h1 + EPSF));
        const float sx = x1 + x2, sy = y1 + y2;
        const int lab = glab[bg];
        unsigned long long best = 0xFFFFFFFFFFFFFFFFull;
        for (int a = lane; a < A; a += 32) {
            const size_t ba = (size_t)b * A + a;
            float4 pb = *(const float4*)(pboxes + ba * 4);
            float w2 = pb.z - pb.x, h2 = pb.w - pb.y;
            float iw = fmaxf(fminf(x2, pb.z) - fmaxf(x1, pb.x), 0.0f);
            float ih = fmaxf(fminf(y2, pb.w) - fmaxf(y1, pb.y), 0.0f);
            float inter = iw * ih;
            float uni   = w1h1 + w2 * h2 - inter + EPSF;
            float iou   = __fdividef(inter, uni);
            float cw    = fmaxf(x2, pb.z) - fminf(x1, pb.x);
            float ch    = fmaxf(y2, pb.w) - fminf(y1, pb.y);
            float c2    = cw * cw + ch * ch + EPSF;
            float dx    = (pb.x + pb.z) - sx, dy = (pb.y + pb.w) - sy;
            float rho2  = (dx * dx + dy * dy) * 0.25f;
            float at2   = atanf(__fdividef(w2, h2 + EPSF));
            float da    = at2 - at1;
            float v     = INV_PI2_4 * da * da;
            float alpha = __fdividef(v, v - iou + (1.0f + EPSF));
            float ciou  = iou - (__fdividef(rho2, c2) + v * alpha);

            bool filt = g_filt[ba] != 0;
            float iouv = filt ? fmaxf(ciou, 0.0f) : 0.0f;

            float base = 0.0f;
            const float4* s4 = (const float4*)(scores + ba * C);
            #pragma unroll 4
            for (int qq = 0; qq < C / 4; qq++) {
                float4 vv = s4[qq];
                base -= fmaxf(__logf(1.0f - __fsqrt_rn(vv.x)), -100.0f);
                base -= fmaxf(__logf(1.0f - __fsqrt_rn(vv.y)), -100.0f);
                base -= fmaxf(__logf(1.0f - __fsqrt_rn(vv.z)), -100.0f);
                base -= fmaxf(__logf(1.0f - __fsqrt_rn(vv.w)), -100.0f);
            }
            float s = scores[ba * C + lab];
            float pp = __fsqrt_rn(s);
            float lp  = fmaxf(0.5f * __logf(s), -100.0f);
            float l1m = fmaxf(__logf(1.0f - pp), -100.0f);
            float cost = base + (l1m - lp) - 3.0f * __logf(iouv + 1e-8f)
                       + 1e6f + (filt ? 0.0f : 1e8f);
            unsigned long long key = (((unsigned long long)fkey(cost)) << 32) | (unsigned int)a;
            if (key < best) best = key;
        }
        #pragma unroll
        for (int o = 16; o > 0; o >>= 1) {
            unsigned long long om = __shfl_xor_sync(0xFFFFFFFFu, best, o);
            if (om < best) best = om;
        }
        if (lane == 0) {
            unsigned int aa = (unsigned int)best;
            atomicAdd(&g_mcnt[(size_t)b * A + aa], 1);
            atomicMin(&g_mfg [(size_t)b * A + aa], g);
            atomicMin(&g_amin[(size_t)b * A + aa],
                      ((best >> 32) << 6) | (unsigned long long)g);
        }
    }
}

// ---------------------------------------------------------------------------
// K3: per anchor: resolve matches, recompute pred_iou. Thread-owned outputs.
// Output layout (tuple order): labels | tboxes | tscores | fg | tgt_idx
// ---------------------------------------------------------------------------
__global__ __launch_bounds__(TILE) void k3(
    const float* __restrict__ pboxes, const int* __restrict__ glab,
    const float* __restrict__ gbox,   const int* __restrict__ gmask,
    float* __restrict__ out)
{
    __shared__ float4 s_box[G];
    __shared__ float4 s_aux[G];   // sx, sy, w1h1, at1
    __shared__ int    s_lab[G], s_val[G];

    const int tid = threadIdx.x;
    const int b   = blockIdx.y;
    if (tid < G) {
        const float* gb = gbox + ((size_t)b * G + tid) * 4;
        float x1 = gb[0], y1 = gb[1], x2 = gb[2], y2 = gb[3];
        s_box[tid] = make_float4(x1, y1, x2, y2);
        float w1 = x2 - x1, h1 = y2 - y1;
        s_aux[tid] = make_float4(x1 + x2, y1 + y2, w1 * h1, atanf(__fdividef(w1, h1 + EPSF)));
        s_lab[tid] = glab[b * G + tid];
        s_val[tid] = gmask[b * G + tid];
    }
    __syncthreads();

    const int blockbase = blockIdx.x * TILE;
    const int count = min(TILE, A - blockbase);
    const int a = blockbase + tid;

    const size_t N  = (size_t)BS * A;
    const size_t bb = (size_t)b * A + blockbase;
    const float4 z4 = make_float4(0.f, 0.f, 0.f, 0.f);

    float piou = 0.0f;
    int   lab  = 0;
    bool  fg   = false;

    if (tid < count) {
        const size_t ba = (size_t)b * A + a;
        const int cnt = g_mcnt[ba];
        fg = (cnt > 0);
        int mg = 0;
        float4 boxv = z4;
        if (fg) {
            mg = (cnt > 1) ? (int)(g_amin[ba] & 63ull) : g_mfg[ba];
            float4 pb = *(const float4*)(pboxes + ba * 4);
            float4 bx = s_box[mg];
            float4 au = s_aux[mg];
            float w2 = pb.z - pb.x, h2 = pb.w - pb.y;
            float iw = fmaxf(fminf(bx.z, pb.z) - fmaxf(bx.x, pb.x), 0.0f);
            float ih = fmaxf(fminf(bx.w, pb.w) - fmaxf(bx.y, pb.y), 0.0f);
            float inter = iw * ih;
            float uni   = au.z + w2 * h2 - inter + EPSF;
            float iou   = __fdividef(inter, uni);
            float cw    = fmaxf(bx.z, pb.z) - fminf(bx.x, pb.x);
            float ch    = fmaxf(bx.w, pb.w) - fminf(bx.y, pb.y);
            float c2    = cw * cw + ch * ch + EPSF;
            float dx    = (pb.x + pb.z) - au.x, dy = (pb.y + pb.w) - au.y;
            float rho2  = (dx * dx + dy * dy) * 0.25f;
            float at2   = atanf(__fdividef(w2, h2 + EPSF));
            float da    = at2 - au.w;
            float v     = INV_PI2_4 * da * da;
            float alpha = __fdividef(v, v - iou + (1.0f + EPSF));
            float ciou  = iou - (__fdividef(rho2, c2) + v * alpha);
            bool filt = (g_filt[ba] != 0);
            piou = (filt && (s_val[mg] != 0)) ? fmaxf(ciou, 0.0f) : 0.0f;
            boxv = bx;
        }
        lab = s_lab[mg];

        out[bb + tid]          = fg ? (float)lab : (float)C;
        out[N * 85 + bb + tid] = fg ? 1.0f : 0.0f;
        out[N * 86 + bb + tid] = fg ? (float)mg : 0.0f;
        ((float4*)(out + N))[bb + tid] = boxv;
    }

    float4* os = (float4*)(out + N * 5 + bb * 80);
    if (count == TILE) {
        #pragma unroll
        for (int k = 0; k < 20; k++) os[k * TILE + tid] = z4;
    } else {
        for (int i = tid; i < count * 20; i += TILE) os[i] = z4;
    }
    __syncthreads();
    if (tid < count && fg)
        out[N * 5 + (bb + tid) * 80 + lab] = piou;
}

// ---------------------------------------------------------------------------
extern "C" void kernel_launch(void* const* d_in, const int* in_sizes, int n_in,
                              void* d_out, int out_size)
{
    const float* scores = (const float*)d_in[0];   // (16, 33600, 80)
    const float* pboxes = (const float*)d_in[1];   // (16, 33600, 4)
    const float* anc    = (const float*)d_in[2];   // (33600, 2)
    const int*   glab   = (const int*)  d_in[3];   // (16, 64, 1)
    const float* gbox   = (const float*)d_in[4];   // (16, 64, 4)
    const int*   gmask  = (const int*)  d_in[5];   // (16, 64, 1)
    const float* strd   = (const float*)d_in[6];   // (16, 33600, 1)
    float* out = (float*)d_out;

    kz<<<1, 1024>>>();
    dim3 gg(NCHUNK, BS);
    k1a<<<gg, TILE>>>(pboxes, anc, gbox, gmask, strd);
    k1b<<<gg, TILE>>>(scores, glab, gbox, gmask);
    k2<<<BS * G, 256>>>(scores, pboxes, glab, gbox, gmask);
    k3<<<gg, TILE>>>(pboxes, glab, gbox, gmask, out);
}

// round 16
// speedup vs baseline: 1.3288x; 1.3288x over previous
#include <cuda_runtime.h>
#include <cstdint>

#define BS 16
#define A  33600
#define G  64
#define C  80
#define EPSF 1e-7f
#define CAP 4096

#define TILE 256
#define NCHUNK ((A + TILE - 1) / TILE)

#define INV_PI2_4 0.4052847345693511f

// Scratch (device globals — no runtime allocation allowed)
__device__ unsigned long long g_key[(size_t)BS * G * CAP]; // candidate (fkey(cost)<<32 | a)
__device__ int                g_cnt[BS * G];               // candidate counts
__device__ float              g_iov[(size_t)BS * G * CAP]; // positive iouv values per (b,g)
__device__ int                g_icnt[BS * G];              // value list counts
__device__ float4             g_fpb  [(size_t)BS * A];     // filt anchors: pred box
__device__ int                g_fa   [(size_t)BS * A];     // filt anchors: anchor index
__device__ unsigned long long g_fmask[(size_t)BS * A];     // filt anchors: ic mask
__device__ int                g_fcnt[BS];                  // filt counts
__device__ unsigned char      g_filt[(size_t)BS * A];      // per-anchor anchor_filter
__device__ unsigned long long g_amin[(size_t)BS * A];      // per-anchor argmin (fkey<<6|g)
__device__ int                g_mcnt[(size_t)BS * A];      // match count per anchor
__device__ int                g_mfg [(size_t)BS * A];      // min matched g per anchor

// Monotone float -> uint32 order-preserving transform
__device__ __forceinline__ unsigned int fkey(float f) {
    unsigned int b = __float_as_uint(f);
    return b ^ ((unsigned int)((int)b >> 31) | 0x80000000u);
}

// ---------------------------------------------------------------------------
// KZ: zero small counters (single block)
// ---------------------------------------------------------------------------
__global__ void kz() {
    int i = threadIdx.x;
    if (i < BS * G) { g_cnt[i] = 0; g_icnt[i] = 0; }
    if (i < BS)     g_fcnt[i] = 0;
}

// ---------------------------------------------------------------------------
// K1a: per (b,a): in-center mask + compaction of filt anchors into per-batch
// lists; also zero-inits per-anchor match state.
// ---------------------------------------------------------------------------
__global__ __launch_bounds__(TILE) void k1a(
    const float* __restrict__ pboxes, const float* __restrict__ anc,
    const float* __restrict__ gbox,   const int*   __restrict__ gmask,
    const float* __restrict__ strd)
{
    __shared__ float2 s_gc[G];
    __shared__ unsigned int s_vm[2];

    const int tid = threadIdx.x;
    const int b   = blockIdx.y;

    if (tid < G) {
        const float* gb = gbox + ((size_t)b * G + tid) * 4;
        s_gc[tid] = make_float2((gb[0] + gb[2]) * 0.5f, (gb[1] + gb[3]) * 0.5f);
        unsigned int bal = __ballot_sync(0xFFFFFFFFu, gmask[b * G + tid] != 0);
        if ((tid & 31) == 0) s_vm[tid >> 5] = bal;
    }
    __syncthreads();

    const int a = blockIdx.x * TILE + tid;
    if (a >= A) return;   // warp-uniform (A % 32 == 0)

    const size_t ba = (size_t)b * A + a;
    g_mcnt[ba] = 0;
    g_mfg [ba] = 0x7FFFFFFF;
    g_amin[ba] = 0xFFFFFFFFFFFFFFFFull;

    const unsigned long long vmask =
        (unsigned long long)s_vm[0] | ((unsigned long long)s_vm[1] << 32);

    const float ax = anc[a * 2 + 0], ay = anc[a * 2 + 1];
    const float cd = strd[ba] * 2.5f;

    unsigned long long mask = 0ull;
    #pragma unroll
    for (int g = 0; g < G; g++) {
        float2 gc = s_gc[g];
        bool ic = (fabsf(ax - gc.x) < cd) && (fabsf(ay - gc.y) < cd);
        mask |= ((unsigned long long)ic) << g;
    }
    mask &= vmask;
    const bool filt = (mask != 0ull);
    g_filt[ba] = filt ? 1 : 0;

    unsigned int fm = __ballot_sync(0xFFFFFFFFu, filt);
    if (filt) {
        const float4 pb = *(const float4*)(pboxes + ba * 4);
        int lane   = tid & 31;
        int leader = __ffs(fm) - 1;
        int basei = 0;
        if (lane == leader) basei = atomicAdd(&g_fcnt[b], __popc(fm));
        basei = __shfl_sync(fm, basei, leader);
        int slot = basei + __popc(fm & ((1u << lane) - 1u));
        size_t off = (size_t)b * A + slot;
        g_fpb  [off] = pb;
        g_fa   [off] = a;
        g_fmask[off] = mask;
    }
}

// ---------------------------------------------------------------------------
// K1b: dense pass over the compacted filt-anchor list.
// Branch-free intersect|ic bitmask, then while over SET BITS only.
// One CIoU per set bit; positive iouv -> per-(b,g) value list; ic bits emit
// cost key + argmin.
// ---------------------------------------------------------------------------
__global__ __launch_bounds__(TILE) void k1b(
    const float* __restrict__ scores, const int* __restrict__ glab,
    const float* __restrict__ gbox,   const int* __restrict__ gmask)
{
    __shared__ float4 s_box[G];
    __shared__ float4 s_aux[G];   // sx, sy, w1h1, at1
    __shared__ int    s_lab[G];
    __shared__ unsigned int s_vm[2];

    const int tid = threadIdx.x;
    const int b   = blockIdx.y;

    if (tid < G) {
        const float* gb = gbox + ((size_t)b * G + tid) * 4;
        float x1 = gb[0], y1 = gb[1], x2 = gb[2], y2 = gb[3];
        s_box[tid] = make_float4(x1, y1, x2, y2);
        float w1 = x2 - x1, h1 = y2 - y1;
        s_aux[tid] = make_float4(x1 + x2, y1 + y2, w1 * h1, atanf(__fdividef(w1, h1 + EPSF)));
        s_lab[tid] = glab[b * G + tid];
        unsigned int bal = __ballot_sync(0xFFFFFFFFu, gmask[b * G + tid] != 0);
        if ((tid & 31) == 0) s_vm[tid >> 5] = bal;
    }
    __syncthreads();

    const int i = blockIdx.x * TILE + tid;
    if (i >= g_fcnt[b]) return;

    const unsigned long long vmask =
        (unsigned long long)s_vm[0] | ((unsigned long long)s_vm[1] << 32);

    const size_t off = (size_t)b * A + i;
    const int a = g_fa[off];
    const float4 pb = g_fpb[off];
    const float w2 = pb.z - pb.x, h2 = pb.w - pb.y;
    const float w2h2 = w2 * h2;
    const float at2  = atanf(__fdividef(w2, h2 + EPSF));
    const unsigned long long mask = g_fmask[off];   // ic & vmask
    const float psx = pb.x + pb.z, psy = pb.y + pb.w;

    const size_t ba = (size_t)b * A + a;
    const float* srow = scores + ba * C;

    // base = sum_c -log1p(-sqrt(s_c))
    float base = 0.0f;
    const float4* srow4 = (const float4*)srow;
    #pragma unroll
    for (int q = 0; q < C / 4; q++) {
        float4 v = srow4[q];
        float ss[4] = {v.x, v.y, v.z, v.w};
        #pragma unroll
        for (int j = 0; j < 4; j++) {
            float p = __fsqrt_rn(ss[j]);
            base -= fmaxf(__logf(1.0f - p), -100.0f);
        }
    }

    // Branch-free intersect mask
    unsigned long long im = 0ull;
    #pragma unroll 8
    for (int g = 0; g < G; g++) {
        const float4 bx = s_box[g];
        bool ix = (fminf(bx.z, pb.z) > fmaxf(bx.x, pb.x)) &&
                  (fminf(bx.w, pb.w) > fmaxf(bx.y, pb.y));
        im |= ((unsigned long long)ix) << g;
    }
    im = (im & vmask) | mask;

    unsigned long long amin = 0xFFFFFFFFFFFFFFFFull;
    unsigned long long mm = im;
    while (mm) {
        int g = __ffsll((long long)mm) - 1;
        mm &= mm - 1;
        const float4 bx = s_box[g];
        const float4 au = s_aux[g];
        float iw = fmaxf(fminf(bx.z, pb.z) - fmaxf(bx.x, pb.x), 0.0f);
        float ih = fmaxf(fminf(bx.w, pb.w) - fmaxf(bx.y, pb.y), 0.0f);
        float inter = iw * ih;
        float uni   = au.z + w2h2 - inter + EPSF;
        float iou   = __fdividef(inter, uni);
        float cw    = fmaxf(bx.z, pb.z) - fminf(bx.x, pb.x);
        float ch    = fmaxf(bx.w, pb.w) - fminf(bx.y, pb.y);
        float c2    = cw * cw + ch * ch + EPSF;
        float dx    = psx - au.x, dy = psy - au.y;
        float rho2  = (dx * dx + dy * dy) * 0.25f;
        float da    = at2 - au.w;
        float v     = INV_PI2_4 * da * da;
        float alpha = __fdividef(v, v - iou + (1.0f + EPSF));
        float ciou  = iou - (__fdividef(rho2, c2) + v * alpha);
        float iouv  = fmaxf(ciou, 0.0f);

        if (iouv > 0.0f) {
            int slot = atomicAdd(&g_icnt[b * G + g], 1);
            if (slot < CAP) g_iov[(size_t)(b * G + g) * CAP + slot] = iouv;
        }

        if ((mask >> g) & 1ull) {
            float s   = srow[s_lab[g]];
            float p   = __fsqrt_rn(s);
            float lp  = fmaxf(0.5f * __logf(s), -100.0f);
            float l1m = fmaxf(__logf(1.0f - p), -100.0f);
            float cost = base + (l1m - lp) - 3.0f * __logf(iouv + 1e-8f);

            unsigned int k32 = fkey(cost);
            unsigned long long pk = (((unsigned long long)k32) << 6) | (unsigned int)g;
            if (pk < amin) amin = pk;

            int slot = atomicAdd(&g_cnt[b * G + g], 1);
            if (slot < CAP)
                g_key[(size_t)(b * G + g) * CAP + slot] =
                    (((unsigned long long)k32) << 32) | (unsigned int)a;
        }
    }
    g_amin[ba] = amin;
}

// ---------------------------------------------------------------------------
// K2: 256-thread block per (b,g). Phase A: parallel value-list scan ->
// per-thread top-10 -> FLOAT merge tree (conflict-free) -> dyn_k.
// Phase B: warp 0 scans keys + dynk shuffle extraction -> T published via
// smem -> ALL 256 threads mark in one pass.
// ---------------------------------------------------------------------------
__global__ __launch_bounds__(256, 6) void k2(
    const float* __restrict__ scores, const float* __restrict__ pboxes,
    const int* __restrict__ glab, const float* __restrict__ gbox,
    const int* __restrict__ gmask)
{
    __shared__ float fc[10 * 256];
    __shared__ int   s_dynk;
    __shared__ unsigned long long s_T;
    __shared__ int   s_wide;   // 1 = all-thread marking with s_T

    const int bg  = blockIdx.x;
    const int tid = threadIdx.x;
    const int b = bg >> 6, g = bg & 63;
    if (gmask[bg] == 0) return;

    // ---- Phase A: top-10 of iou values -> dyn_k ----
    const int n_i = min(g_icnt[bg], CAP);
    const float* vl = g_iov + (size_t)bg * CAP;
    float top[10];
    #pragma unroll
    for (int j = 0; j < 10; j++) top[j] = 0.0f;   // iouv >= 0; zero-padding exact
    for (int i = tid; i < n_i; i += 256) {
        float v = vl[i];
        if (v > top[9]) {
            top[9] = v;
            #pragma unroll
            for (int j = 8; j >= 0; j--)
                if (top[j + 1] > top[j]) { float t = top[j]; top[j] = top[j + 1]; top[j + 1] = t; }
        }
    }
    #pragma unroll
    for (int j = 0; j < 10; j++) fc[j * 256 + tid] = top[j];
    __syncthreads();

    for (int s = 128; s >= 1; s >>= 1) {
        if (tid < s) {
            #pragma unroll
            for (int j = 0; j < 10; j++) {
                float v = fc[j * 256 + tid + s];
                if (v > top[9]) {
                    top[9] = v;
                    #pragma unroll
                    for (int t = 8; t >= 0; t--)
                        if (top[t + 1] > top[t]) { float tt = top[t]; top[t] = top[t + 1]; top[t + 1] = tt; }
                }
            }
            #pragma unroll
            for (int j = 0; j < 10; j++) fc[j * 256 + tid] = top[j];
        }
        __syncthreads();
    }
    if (tid == 0) {
        float sum = 0.0f;
        #pragma unroll
        for (int j = 0; j < 10; j++) sum += top[j];   // descending = top_k sum order
        s_dynk = max((int)(sum + 0.5f), 1);
        s_wide = 0;
    }
    __syncthreads();
    const int dynk = s_dynk;

    // ---- Phase B: warp 0 computes T; all threads mark ----
    const int n = min(g_cnt[bg], CAP);
    const unsigned long long* kl = g_key + (size_t)bg * CAP;

    if (tid < 32) {
        const int lane = tid;
        if (n > 0) {
            unsigned long long bot[10];
            #pragma unroll
            for (int j = 0; j < 10; j++) bot[j] = 0xFFFFFFFFFFFFFFFFull;
            for (int i = lane; i < n; i += 32) {
                unsigned long long key = kl[i];
                if (key < bot[9]) {
                    bot[9] = key;
                    #pragma unroll
                    for (int j = 8; j >= 0; j--)
                        if (bot[j + 1] < bot[j]) { unsigned long long t = bot[j]; bot[j] = bot[j + 1]; bot[j + 1] = t; }
                }
            }
            unsigned long long T = 0xFFFFFFFFFFFFFFFFull;
            for (int r = 0; r < dynk; r++) {
                unsigned long long m = bot[0];
                #pragma unroll
                for (int o = 16; o > 0; o >>= 1) {
                    unsigned long long om = __shfl_xor_sync(0xFFFFFFFFu, m, o);
                    if (om < m) m = om;
                }
                T = m;
                if (bot[0] == m) {               // keys unique; static shift-down
                    #pragma unroll
                    for (int t = 0; t < 9; t++) bot[t] = bot[t + 1];
                    bot[9] = 0xFFFFFFFFFFFFFFFFull;
                }
            }
            if (lane == 0) { s_T = T; s_wide = 1; }
        } else {
            // Fallback (statistically unreachable): warp-level global row min.
            const float* gb = gbox + (size_t)bg * 4;
            const float x1 = gb[0], y1 = gb[1], x2 = gb[2], y2 = gb[3];
            const float w1 = x2 - x1, h1 = y2 - y1, w1h1 = w1 * h1;
            const float at1 = atanf(__fdividef(w1, h1 + EPSF));
            const float sx = x1 + x2, sy = y1 + y2;
            const int lab = glab[bg];
            unsigned long long best = 0xFFFFFFFFFFFFFFFFull;
            for (int a = lane; a < A; a += 32) {
                const size_t ba = (size_t)b * A + a;
                float4 pb = *(const float4*)(pboxes + ba * 4);
                float w2 = pb.z - pb.x, h2 = pb.w - pb.y;
                float iw = fmaxf(fminf(x2, pb.z) - fmaxf(x1, pb.x), 0.0f);
                float ih = fmaxf(fminf(y2, pb.w) - fmaxf(y1, pb.y), 0.0f);
                float inter = iw * ih;
                float uni   = w1h1 + w2 * h2 - inter + EPSF;
                float iou   = __fdividef(inter, uni);
                float cw    = fmaxf(x2, pb.z) - fminf(x1, pb.x);
                float ch    = fmaxf(y2, pb.w) - fminf(y1, pb.y);
                float c2    = cw * cw + ch * ch + EPSF;
                float dx    = (pb.x + pb.z) - sx, dy = (pb.y + pb.w) - sy;
                float rho2  = (dx * dx + dy * dy) * 0.25f;
                float at2   = atanf(__fdividef(w2, h2 + EPSF));
                float da    = at2 - at1;
                float v     = INV_PI2_4 * da * da;
                float alpha = __fdividef(v, v - iou + (1.0f + EPSF));
                float ciou  = iou - (__fdividef(rho2, c2) + v * alpha);

                bool filt = g_filt[ba] != 0;
                float iouv = filt ? fmaxf(ciou, 0.0f) : 0.0f;

                float base = 0.0f;
                const float4* s4 = (const float4*)(scores + ba * C);
                #pragma unroll 4
                for (int qq = 0; qq < C / 4; qq++) {
                    float4 vv = s4[qq];
                    base -= fmaxf(__logf(1.0f - __fsqrt_rn(vv.x)), -100.0f);
                    base -= fmaxf(__logf(1.0f - __fsqrt_rn(vv.y)), -100.0f);
                    base -= fmaxf(__logf(1.0f - __fsqrt_rn(vv.z)), -100.0f);
                    base -= fmaxf(__logf(1.0f - __fsqrt_rn(vv.w)), -100.0f);
                }
                float s = scores[ba * C + lab];
                float pp = __fsqrt_rn(s);
                float lp  = fmaxf(0.5f * __logf(s), -100.0f);
                float l1m = fmaxf(__logf(1.0f - pp), -100.0f);
                float cost = base + (l1m - lp) - 3.0f * __logf(iouv + 1e-8f)
                           + 1e6f + (filt ? 0.0f : 1e8f);
                unsigned long long key = (((unsigned long long)fkey(cost)) << 32) | (unsigned int)a;
                if (key < best) best = key;
            }
            #pragma unroll
            for (int o = 16; o > 0; o >>= 1) {
                unsigned long long om = __shfl_xor_sync(0xFFFFFFFFu, best, o);
                if (om < best) best = om;
            }
            if (lane == 0) {
                unsigned int aa = (unsigned int)best;
                atomicAdd(&g_mcnt[(size_t)b * A + aa], 1);
                atomicMin(&g_mfg [(size_t)b * A + aa], g);
                atomicMin(&g_amin[(size_t)b * A + aa],
                          ((best >> 32) << 6) | (unsigned long long)g);
            }
        }
    }
    __syncthreads();

    if (s_wide) {
        const unsigned long long T = s_T;
        for (int i = tid; i < n; i += 256) {
            unsigned long long key = kl[i];
            if (key <= T) {
                unsigned int aa = (unsigned int)key;
                atomicAdd(&g_mcnt[(size_t)b * A + aa], 1);
                atomicMin(&g_mfg [(size_t)b * A + aa], g);
            }
        }
    }
}

// ---------------------------------------------------------------------------
// K3: per anchor: resolve matches, recompute pred_iou. Thread-owned outputs.
// Output layout (tuple order): labels | tboxes | tscores | fg | tgt_idx
// ---------------------------------------------------------------------------
__global__ __launch_bounds__(TILE) void k3(
    const float* __restrict__ pboxes, const int* __restrict__ glab,
    const float* __restrict__ gbox,   const int* __restrict__ gmask,
    float* __restrict__ out)
{
    __shared__ float4 s_box[G];
    __shared__ float4 s_aux[G];   // sx, sy, w1h1, at1
    __shared__ int    s_lab[G], s_val[G];

    const int tid = threadIdx.x;
    const int b   = blockIdx.y;
    if (tid < G) {
        const float* gb = gbox + ((size_t)b * G + tid) * 4;
        float x1 = gb[0], y1 = gb[1], x2 = gb[2], y2 = gb[3];
        s_box[tid] = make_float4(x1, y1, x2, y2);
        float w1 = x2 - x1, h1 = y2 - y1;
        s_aux[tid] = make_float4(x1 + x2, y1 + y2, w1 * h1, atanf(__fdividef(w1, h1 + EPSF)));
        s_lab[tid] = glab[b * G + tid];
        s_val[tid] = gmask[b * G + tid];
    }
    __syncthreads();

    const int blockbase = blockIdx.x * TILE;
    const int count = min(TILE, A - blockbase);
    const int a = blockbase + tid;

    const size_t N  = (size_t)BS * A;
    const size_t bb = (size_t)b * A + blockbase;
    const float4 z4 = make_float4(0.f, 0.f, 0.f, 0.f);

    float piou = 0.0f;
    int   lab  = 0;
    bool  fg   = false;

    if (tid < count) {
        const size_t ba = (size_t)b * A + a;
        const int cnt = g_mcnt[ba];
        fg = (cnt > 0);
        int mg = 0;
        float4 boxv = z4;
        if (fg) {
            mg = (cnt > 1) ? (int)(g_amin[ba] & 63ull) : g_mfg[ba];
            float4 pb = *(const float4*)(pboxes + ba * 4);
            float4 bx = s_box[mg];
            float4 au = s_aux[mg];
            float w2 = pb.z - pb.x, h2 = pb.w - pb.y;
            float iw = fmaxf(fminf(bx.z, pb.z) - fmaxf(bx.x, pb.x), 0.0f);
            float ih = fmaxf(fminf(bx.w, pb.w) - fmaxf(bx.y, pb.y), 0.0f);
            float inter = iw * ih;
            float uni   = au.z + w2 * h2 - inter + EPSF;
            float iou   = __fdividef(inter, uni);
            float cw    = fmaxf(bx.z, pb.z) - fminf(bx.x, pb.x);
            float ch    = fmaxf(bx.w, pb.w) - fminf(bx.y, pb.y);
            float c2    = cw * cw + ch * ch + EPSF;
            float dx    = (pb.x + pb.z) - au.x, dy = (pb.y + pb.w) - au.y;
            float rho2  = (dx * dx + dy * dy) * 0.25f;
            float at2   = atanf(__fdividef(w2, h2 + EPSF));
            float da    = at2 - au.w;
            float v     = INV_PI2_4 * da * da;
            float alpha = __fdividef(v, v - iou + (1.0f + EPSF));
            float ciou  = iou - (__fdividef(rho2, c2) + v * alpha);
            bool filt = (g_filt[ba] != 0);
            piou = (filt && (s_val[mg] != 0)) ? fmaxf(ciou, 0.0f) : 0.0f;
            boxv = bx;
        }
        lab = s_lab[mg];

        out[bb + tid]          = fg ? (float)lab : (float)C;
        out[N * 85 + bb + tid] = fg ? 1.0f : 0.0f;
        out[N * 86 + bb + tid] = fg ? (float)mg : 0.0f;
        ((float4*)(out + N))[bb + tid] = boxv;
    }

    float4* os = (float4*)(out + N * 5 + bb * 80);
    if (count == TILE) {
        #pragma unroll
        for (int k = 0; k < 20; k++) os[k * TILE + tid] = z4;
    } else {
        for (int i = tid; i < count * 20; i += TILE) os[i] = z4;
    }
    __syncthreads();
    if (tid < count && fg)
        out[N * 5 + (bb + tid) * 80 + lab] = piou;
}

// ---------------------------------------------------------------------------
extern "C" void kernel_launch(void* const* d_in, const int* in_sizes, int n_in,
                              void* d_out, int out_size)
{
    const float* scores = (const float*)d_in[0];   // (16, 33600, 80)
    const float* pboxes = (const float*)d_in[1];   // (16, 33600, 4)
    const float* anc    = (const float*)d_in[2];   // (33600, 2)
    const int*   glab   = (const int*)  d_in[3];   // (16, 64, 1)
    const float* gbox   = (const float*)d_in[4];   // (16, 64, 4)
    const int*   gmask  = (const int*)  d_in[5];   // (16, 64, 1)
    const float* strd   = (const float*)d_in[6];   // (16, 33600, 1)
    float* out = (float*)d_out;

    kz<<<1, 1024>>>();
    dim3 gg(NCHUNK, BS);
    k1a<<<gg, TILE>>>(pboxes, anc, gbox, gmask, strd);
    k1b<<<gg, TILE>>>(scores, glab, gbox, gmask);
    k2<<<BS * G, 256>>>(scores, pboxes, glab, gbox, gmask);
    k3<<<gg, TILE>>>(pboxes, glab, gbox, gmask, out);
}

// round 17
// speedup vs baseline: 1.3872x; 1.0440x over previous
#include <cuda_runtime.h>
#include <cstdint>

#define BS 16
#define A  33600
#define G  64
#define C  80
#define EPSF 1e-7f
#define CAP 4096

#define TILE 256
#define NCHUNK ((A + TILE - 1) / TILE)

#define INV_PI2_4 0.4052847345693511f

// tscores zero-fill slicing (float4 units). Total = BS*A*80/4 = 10,752,000.
#define TS4TOT   10752000u
#define NT_AB    540672u            // threads in k1a/k1b grids (2112 blocks x 256)
#define TS_S1    4325376u           // k1a slice end   (8 * NT_AB)
#define TS_S2    8650752u           // k1b slice end   (16 * NT_AB)

// Scratch (device globals — no runtime allocation allowed)
__device__ unsigned long long g_key[(size_t)BS * G * CAP]; // candidate (fkey(cost)<<32 | a)
__device__ int                g_cnt[BS * G];               // candidate counts
__device__ float              g_iov[(size_t)BS * G * CAP]; // positive iouv values per (b,g)
__device__ int                g_icnt[BS * G];              // value list counts
__device__ float4             g_fpb  [(size_t)BS * A];     // filt anchors: pred box
__device__ int                g_fa   [(size_t)BS * A];     // filt anchors: anchor index
__device__ unsigned long long g_fmask[(size_t)BS * A];     // filt anchors: ic mask
__device__ int                g_fcnt[BS];                  // filt counts
__device__ unsigned char      g_filt[(size_t)BS * A];      // per-anchor anchor_filter
__device__ unsigned long long g_amin[(size_t)BS * A];      // per-anchor argmin (fkey<<6|g)
__device__ int                g_mcnt[(size_t)BS * A];      // match count per anchor
__device__ int                g_mfg [(size_t)BS * A];      // min matched g per anchor

// Monotone float -> uint32 order-preserving transform
__device__ __forceinline__ unsigned int fkey(float f) {
    unsigned int b = __float_as_uint(f);
    return b ^ ((unsigned int)((int)b >> 31) | 0x80000000u);
}

// ---------------------------------------------------------------------------
// KZ: zero small counters (single block)
// ---------------------------------------------------------------------------
__global__ void kz() {
    int i = threadIdx.x;
    if (i < BS * G) { g_cnt[i] = 0; g_icnt[i] = 0; }
    if (i < BS)     g_fcnt[i] = 0;
}

// ---------------------------------------------------------------------------
// K1a: per (b,a): in-center mask + compaction of filt anchors into per-batch
// lists; zero-inits per-anchor match state; zeroes tscores slice 1 (overlaps
// the issue-bound compute with otherwise-idle DRAM).
// ---------------------------------------------------------------------------
__global__ __launch_bounds__(TILE) void k1a(
    const float* __restrict__ pboxes, const float* __restrict__ anc,
    const float* __restrict__ gbox,   const int*   __restrict__ gmask,
    const float* __restrict__ strd,   float* __restrict__ ts)
{
    __shared__ float2 s_gc[G];
    __shared__ unsigned int s_vm[2];

    const int tid = threadIdx.x;
    const int b   = blockIdx.y;

    // tscores zero-fill slice 1: exact cover, coalesced
    {
        float4* ts4 = (float4*)ts;
        const float4 z4 = make_float4(0.f, 0.f, 0.f, 0.f);
        size_t gid = ((size_t)b * NCHUNK + blockIdx.x) * TILE + tid;
        #pragma unroll
        for (int k = 0; k < 8; k++)
            ts4[gid + (size_t)k * NT_AB] = z4;
    }

    if (tid < G) {
        const float* gb = gbox + ((size_t)b * G + tid) * 4;
        s_gc[tid] = make_float2((gb[0] + gb[2]) * 0.5f, (gb[1] + gb[3]) * 0.5f);
        unsigned int bal = __ballot_sync(0xFFFFFFFFu, gmask[b * G + tid] != 0);
        if ((tid & 31) == 0) s_vm[tid >> 5] = bal;
    }
    __syncthreads();

    const int a = blockIdx.x * TILE + tid;
    if (a >= A) return;   // warp-uniform (A % 32 == 0)

    const size_t ba = (size_t)b * A + a;
    g_mcnt[ba] = 0;
    g_mfg [ba] = 0x7FFFFFFF;
    g_amin[ba] = 0xFFFFFFFFFFFFFFFFull;

    const unsigned long long vmask =
        (unsigned long long)s_vm[0] | ((unsigned long long)s_vm[1] << 32);

    const float ax = anc[a * 2 + 0], ay = anc[a * 2 + 1];
    const float cd = strd[ba] * 2.5f;

    unsigned long long mask = 0ull;
    #pragma unroll
    for (int g = 0; g < G; g++) {
        float2 gc = s_gc[g];
        bool ic = (fabsf(ax - gc.x) < cd) && (fabsf(ay - gc.y) < cd);
        mask |= ((unsigned long long)ic) << g;
    }
    mask &= vmask;
    const bool filt = (mask != 0ull);
    g_filt[ba] = filt ? 1 : 0;

    unsigned int fm = __ballot_sync(0xFFFFFFFFu, filt);
    if (filt) {
        const float4 pb = *(const float4*)(pboxes + ba * 4);
        int lane   = tid & 31;
        int leader = __ffs(fm) - 1;
        int basei = 0;
        if (lane == leader) basei = atomicAdd(&g_fcnt[b], __popc(fm));
        basei = __shfl_sync(fm, basei, leader);
        int slot = basei + __popc(fm & ((1u << lane) - 1u));
        size_t off = (size_t)b * A + slot;
        g_fpb  [off] = pb;
        g_fa   [off] = a;
        g_fmask[off] = mask;
    }
}

// ---------------------------------------------------------------------------
// K1b: dense pass over the compacted filt-anchor list + tscores slice 2.
// Branch-free intersect|ic bitmask, then while over SET BITS only.
// ---------------------------------------------------------------------------
__global__ __launch_bounds__(TILE) void k1b(
    const float* __restrict__ scores, const int* __restrict__ glab,
    const float* __restrict__ gbox,   const int* __restrict__ gmask,
    float* __restrict__ ts)
{
    __shared__ float4 s_box[G];
    __shared__ float4 s_aux[G];   // sx, sy, w1h1, at1
    __shared__ int    s_lab[G];
    __shared__ unsigned int s_vm[2];

    const int tid = threadIdx.x;
    const int b   = blockIdx.y;

    // tscores zero-fill slice 2 (runs even for threads that exit early)
    {
        float4* ts4 = (float4*)ts;
        const float4 z4 = make_float4(0.f, 0.f, 0.f, 0.f);
        size_t gid = TS_S1 + ((size_t)b * NCHUNK + blockIdx.x) * TILE + tid;
        #pragma unroll
        for (int k = 0; k < 8; k++)
            ts4[gid + (size_t)k * NT_AB] = z4;
    }

    if (tid < G) {
        const float* gb = gbox + ((size_t)b * G + tid) * 4;
        float x1 = gb[0], y1 = gb[1], x2 = gb[2], y2 = gb[3];
        s_box[tid] = make_float4(x1, y1, x2, y2);
        float w1 = x2 - x1, h1 = y2 - y1;
        s_aux[tid] = make_float4(x1 + x2, y1 + y2, w1 * h1, atanf(__fdividef(w1, h1 + EPSF)));
        s_lab[tid] = glab[b * G + tid];
        unsigned int bal = __ballot_sync(0xFFFFFFFFu, gmask[b * G + tid] != 0);
        if ((tid & 31) == 0) s_vm[tid >> 5] = bal;
    }
    __syncthreads();

    const int i = blockIdx.x * TILE + tid;
    if (i >= g_fcnt[b]) return;

    const unsigned long long vmask =
        (unsigned long long)s_vm[0] | ((unsigned long long)s_vm[1] << 32);

    const size_t off = (size_t)b * A + i;
    const int a = g_fa[off];
    const float4 pb = g_fpb[off];
    const float w2 = pb.z - pb.x, h2 = pb.w - pb.y;
    const float w2h2 = w2 * h2;
    const float at2  = atanf(__fdividef(w2, h2 + EPSF));
    const unsigned long long mask = g_fmask[off];   // ic & vmask
    const float psx = pb.x + pb.z, psy = pb.y + pb.w;

    const size_t ba = (size_t)b * A + a;
    const float* srow = scores + ba * C;

    // base = sum_c -log1p(-sqrt(s_c))
    float base = 0.0f;
    const float4* srow4 = (const float4*)srow;
    #pragma unroll
    for (int q = 0; q < C / 4; q++) {
        float4 v = srow4[q];
        float ss[4] = {v.x, v.y, v.z, v.w};
        #pragma unroll
        for (int j = 0; j < 4; j++) {
            float p = __fsqrt_rn(ss[j]);
            base -= fmaxf(__logf(1.0f - p), -100.0f);
        }
    }

    // Branch-free intersect mask
    unsigned long long im = 0ull;
    #pragma unroll 8
    for (int g = 0; g < G; g++) {
        const float4 bx = s_box[g];
        bool ix = (fminf(bx.z, pb.z) > fmaxf(bx.x, pb.x)) &&
                  (fminf(bx.w, pb.w) > fmaxf(bx.y, pb.y));
        im |= ((unsigned long long)ix) << g;
    }
    im = (im & vmask) | mask;

    unsigned long long amin = 0xFFFFFFFFFFFFFFFFull;
    unsigned long long mm = im;
    while (mm) {
        int g = __ffsll((long long)mm) - 1;
        mm &= mm - 1;
        const float4 bx = s_box[g];
        const float4 au = s_aux[g];
        float iw = fmaxf(fminf(bx.z, pb.z) - fmaxf(bx.x, pb.x), 0.0f);
        float ih = fmaxf(fminf(bx.w, pb.w) - fmaxf(bx.y, pb.y), 0.0f);
        float inter = iw * ih;
        float uni   = au.z + w2h2 - inter + EPSF;
        float iou   = __fdividef(inter, uni);
        float cw    = fmaxf(bx.z, pb.z) - fminf(bx.x, pb.x);
        float ch    = fmaxf(bx.w, pb.w) - fminf(bx.y, pb.y);
        float c2    = cw * cw + ch * ch + EPSF;
        float dx    = psx - au.x, dy = psy - au.y;
        float rho2  = (dx * dx + dy * dy) * 0.25f;
        float da    = at2 - au.w;
        float v     = INV_PI2_4 * da * da;
        float alpha = __fdividef(v, v - iou + (1.0f + EPSF));
        float ciou  = iou - (__fdividef(rho2, c2) + v * alpha);
        float iouv  = fmaxf(ciou, 0.0f);

        if (iouv > 0.0f) {
            int slot = atomicAdd(&g_icnt[b * G + g], 1);
            if (slot < CAP) g_iov[(size_t)(b * G + g) * CAP + slot] = iouv;
        }

        if ((mask >> g) & 1ull) {
            float s   = srow[s_lab[g]];
            float p   = __fsqrt_rn(s);
            float lp  = fmaxf(0.5f * __logf(s), -100.0f);
            float l1m = fmaxf(__logf(1.0f - p), -100.0f);
            float cost = base + (l1m - lp) - 3.0f * __logf(iouv + 1e-8f);

            unsigned int k32 = fkey(cost);
            unsigned long long pk = (((unsigned long long)k32) << 6) | (unsigned int)g;
            if (pk < amin) amin = pk;

            int slot = atomicAdd(&g_cnt[b * G + g], 1);
            if (slot < CAP)
                g_key[(size_t)(b * G + g) * CAP + slot] =
                    (((unsigned long long)k32) << 32) | (unsigned int)a;
        }
    }
    g_amin[ba] = amin;
}

// ---------------------------------------------------------------------------
// K2: 256-thread block per (b,g) + tscores slice 3 (before the early exit).
// Phase A: parallel value-list scan -> float merge tree -> dyn_k.
// Phase B: warp 0 computes T; ALL threads mark in one pass.
// ---------------------------------------------------------------------------
__global__ __launch_bounds__(256, 6) void k2(
    const float* __restrict__ scores, const float* __restrict__ pboxes,
    const int* __restrict__ glab, const float* __restrict__ gbox,
    const int* __restrict__ gmask, float* __restrict__ ts)
{
    __shared__ float fc[10 * 256];
    __shared__ int   s_dynk;
    __shared__ unsigned long long s_T;
    __shared__ int   s_wide;

    const int bg  = blockIdx.x;
    const int tid = threadIdx.x;
    const int b = bg >> 6, g = bg & 63;

    // tscores zero-fill slice 3 (all blocks, including gmask==0 ones)
    {
        float4* ts4 = (float4*)ts;
        const float4 z4 = make_float4(0.f, 0.f, 0.f, 0.f);
        for (size_t idx = TS_S2 + (size_t)bg * 256 + tid; idx < TS4TOT; idx += 262144u)
            ts4[idx] = z4;
    }

    if (gmask[bg] == 0) return;

    // ---- Phase A: top-10 of iou values -> dyn_k ----
    const int n_i = min(g_icnt[bg], CAP);
    const float* vl = g_iov + (size_t)bg * CAP;
    float top[10];
    #pragma unroll
    for (int j = 0; j < 10; j++) top[j] = 0.0f;   // iouv >= 0; zero-padding exact
    for (int i = tid; i < n_i; i += 256) {
        float v = vl[i];
        if (v > top[9]) {
            top[9] = v;
            #pragma unroll
            for (int j = 8; j >= 0; j--)
                if (top[j + 1] > top[j]) { float t = top[j]; top[j] = top[j + 1]; top[j + 1] = t; }
        }
    }
    #pragma unroll
    for (int j = 0; j < 10; j++) fc[j * 256 + tid] = top[j];
    __syncthreads();

    for (int s = 128; s >= 1; s >>= 1) {
        if (tid < s) {
            #pragma unroll
            for (int j = 0; j < 10; j++) {
                float v = fc[j * 256 + tid + s];
                if (v > top[9]) {
                    top[9] = v;
                    #pragma unroll
                    for (int t = 8; t >= 0; t--)
                        if (top[t + 1] > top[t]) { float tt = top[t]; top[t] = top[t + 1]; top[t + 1] = tt; }
                }
            }
            #pragma unroll
            for (int j = 0; j < 10; j++) fc[j * 256 + tid] = top[j];
        }
        __syncthreads();
    }
    if (tid == 0) {
        float sum = 0.0f;
        #pragma unroll
        for (int j = 0; j < 10; j++) sum += top[j];   // descending = top_k sum order
        s_dynk = max((int)(sum + 0.5f), 1);
        s_wide = 0;
    }
    __syncthreads();
    const int dynk = s_dynk;

    // ---- Phase B: warp 0 computes T; all threads mark ----
    const int n = min(g_cnt[bg], CAP);
    const unsigned long long* kl = g_key + (size_t)bg * CAP;

    if (tid < 32) {
        const int lane = tid;
        if (n > 0) {
            unsigned long long bot[10];
            #pragma unroll
            for (int j = 0; j < 10; j++) bot[j] = 0xFFFFFFFFFFFFFFFFull;
            for (int i = lane; i < n; i += 32) {
                unsigned long long key = kl[i];
                if (key < bot[9]) {
                    bot[9] = key;
                    #pragma unroll
                    for (int j = 8; j >= 0; j--)
                        if (bot[j + 1] < bot[j]) { unsigned long long t = bot[j]; bot[j] = bot[j + 1]; bot[j + 1] = t; }
                }
            }
            unsigned long long T = 0xFFFFFFFFFFFFFFFFull;
            for (int r = 0; r < dynk; r++) {
                unsigned long long m = bot[0];
                #pragma unroll
                for (int o = 16; o > 0; o >>= 1) {
                    unsigned long long om = __shfl_xor_sync(0xFFFFFFFFu, m, o);
                    if (om < m) m = om;
                }
                T = m;
                if (bot[0] == m) {               // keys unique; static shift-down
                    #pragma unroll
                    for (int t = 0; t < 9; t++) bot[t] = bot[t + 1];
                    bot[9] = 0xFFFFFFFFFFFFFFFFull;
                }
            }
            if (lane == 0) { s_T = T; s_wide = 1; }
        } else {
            // Fallback (statistically unreachable): warp-level global row min.
            const float* gb = gbox + (size_t)bg * 4;
            const float x1 = gb[0], y1 = gb[1], x2 = gb[2], y2 = gb[3];
            const float w1 = x2 - x1, h1 = y2 - y1, w1h1 = w1 * h1;
            const float at1 = atanf(__fdividef(w1, h1 + EPSF));
            const float sx = x1 + x2, sy = y1 + y2;
            const int lab = glab[bg];
            unsigned long long best = 0xFFFFFFFFFFFFFFFFull;
            for (int a = lane; a < A; a += 32) {
                const size_t ba = (size_t)b * A + a;
                float4 pb = *(const float4*)(pboxes + ba * 4);
                float w2 = pb.z - pb.x, h2 = pb.w - pb.y;
                float iw = fmaxf(fminf(x2, pb.z) - fmaxf(x1, pb.x), 0.0f);
                float ih = fmaxf(fminf(y2, pb.w) - fmaxf(y1, pb.y), 0.0f);
                float inter = iw * ih;
                float uni   = w1h1 + w2 * h2 - inter + EPSF;
                float iou   = __fdividef(inter, uni);
                float cw    = fmaxf(x2, pb.z) - fminf(x1, pb.x);
                float ch    = fmaxf(y2, pb.w) - fminf(y1, pb.y);
                float c2    = cw * cw + ch * ch + EPSF;
                float dx    = (pb.x + pb.z) - sx, dy = (pb.y + pb.w) - sy;
                float rho2  = (dx * dx + dy * dy) * 0.25f;
                float at2   = atanf(__fdividef(w2, h2 + EPSF));
                float da    = at2 - at1;
                float v     = INV_PI2_4 * da * da;
                float alpha = __fdividef(v, v - iou + (1.0f + EPSF));
                float ciou  = iou - (__fdividef(rho2, c2) + v * alpha);

                bool filt = g_filt[ba] != 0;
                float iouv = filt ? fmaxf(ciou, 0.0f) : 0.0f;

                float base = 0.0f;
                const float4* s4 = (const float4*)(scores + ba * C);
                #pragma unroll 4
                for (int qq = 0; qq < C / 4; qq++) {
                    float4 vv = s4[qq];
                    base -= fmaxf(__logf(1.0f - __fsqrt_rn(vv.x)), -100.0f);
                    base -= fmaxf(__logf(1.0f - __fsqrt_rn(vv.y)), -100.0f);
                    base -= fmaxf(__logf(1.0f - __fsqrt_rn(vv.z)), -100.0f);
                    base -= fmaxf(__logf(1.0f - __fsqrt_rn(vv.w)), -100.0f);
                }
                float s = scores[ba * C + lab];
                float pp = __fsqrt_rn(s);
                float lp  = fmaxf(0.5f * __logf(s), -100.0f);
                float l1m = fmaxf(__logf(1.0f - pp), -100.0f);
                float cost = base + (l1m - lp) - 3.0f * __logf(iouv + 1e-8f)
                           + 1e6f + (filt ? 0.0f : 1e8f);
                unsigned long long key = (((unsigned long long)fkey(cost)) << 32) | (unsigned int)a;
                if (key < best) best = key;
            }
            #pragma unroll
            for (int o = 16; o > 0; o >>= 1) {
                unsigned long long om = __shfl_xor_sync(0xFFFFFFFFu, best, o);
                if (om < best) best = om;
            }
            if (lane == 0) {
                unsigned int aa = (unsigned int)best;
                atomicAdd(&g_mcnt[(size_t)b * A + aa], 1);
                atomicMin(&g_mfg [(size_t)b * A + aa], g);
                atomicMin(&g_amin[(size_t)b * A + aa],
                          ((best >> 32) << 6) | (unsigned long long)g);
            }
        }
    }
    __syncthreads();

    if (s_wide) {
        const unsigned long long T = s_T;
        for (int i = tid; i < n; i += 256) {
            unsigned long long key = kl[i];
            if (key <= T) {
                unsigned int aa = (unsigned int)key;
                atomicAdd(&g_mcnt[(size_t)b * A + aa], 1);
                atomicMin(&g_mfg [(size_t)b * A + aa], g);
            }
        }
    }
}

// ---------------------------------------------------------------------------
// K3: per anchor: resolve matches, recompute pred_iou. Thread-owned outputs.
// tscores already zeroed by k1a/k1b/k2; only the sparse scatter remains.
// Output layout (tuple order): labels | tboxes | tscores | fg | tgt_idx
// ---------------------------------------------------------------------------
__global__ __launch_bounds__(TILE) void k3(
    const float* __restrict__ pboxes, const int* __restrict__ glab,
    const float* __restrict__ gbox,   const int* __restrict__ gmask,
    float* __restrict__ out)
{
    __shared__ float4 s_box[G];
    __shared__ float4 s_aux[G];   // sx, sy, w1h1, at1
    __shared__ int    s_lab[G], s_val[G];

    const int tid = threadIdx.x;
    const int b   = blockIdx.y;
    if (tid < G) {
        const float* gb = gbox + ((size_t)b * G + tid) * 4;
        float x1 = gb[0], y1 = gb[1], x2 = gb[2], y2 = gb[3];
        s_box[tid] = make_float4(x1, y1, x2, y2);
        float w1 = x2 - x1, h1 = y2 - y1;
        s_aux[tid] = make_float4(x1 + x2, y1 + y2, w1 * h1, atanf(__fdividef(w1, h1 + EPSF)));
        s_lab[tid] = glab[b * G + tid];
        s_val[tid] = gmask[b * G + tid];
    }
    __syncthreads();

    const int a = blockIdx.x * TILE + tid;
    if (a >= A) return;

    const size_t N  = (size_t)BS * A;
    const size_t ba = (size_t)b * A + a;
    const float4 z4 = make_float4(0.f, 0.f, 0.f, 0.f);

    const int cnt = g_mcnt[ba];
    const bool fg = (cnt > 0);
    int mg = 0;
    float piou = 0.0f;
    float4 boxv = z4;
    if (fg) {
        mg = (cnt > 1) ? (int)(g_amin[ba] & 63ull) : g_mfg[ba];
        float4 pb = *(const float4*)(pboxes + ba * 4);
        float4 bx = s_box[mg];
        float4 au = s_aux[mg];
        float w2 = pb.z - pb.x, h2 = pb.w - pb.y;
        float iw = fmaxf(fminf(bx.z, pb.z) - fmaxf(bx.x, pb.x), 0.0f);
        float ih = fmaxf(fminf(bx.w, pb.w) - fmaxf(bx.y, pb.y), 0.0f);
        float inter = iw * ih;
        float uni   = au.z + w2 * h2 - inter + EPSF;
        float iou   = __fdividef(inter, uni);
        float cw    = fmaxf(bx.z, pb.z) - fminf(bx.x, pb.x);
        float ch    = fmaxf(bx.w, pb.w) - fminf(bx.y, pb.y);
        float c2    = cw * cw + ch * ch + EPSF;
        float dx    = (pb.x + pb.z) - au.x, dy = (pb.y + pb.w) - au.y;
        float rho2  = (dx * dx + dy * dy) * 0.25f;
        float at2   = atanf(__fdividef(w2, h2 + EPSF));
        float da    = at2 - au.w;
        float v     = INV_PI2_4 * da * da;
        float alpha = __fdividef(v, v - iou + (1.0f + EPSF));
        float ciou  = iou - (__fdividef(rho2, c2) + v * alpha);
        bool filt = (g_filt[ba] != 0);
        piou = (filt && (s_val[mg] != 0)) ? fmaxf(ciou, 0.0f) : 0.0f;
        boxv = bx;
    }
    const int lab = s_lab[mg];

    out[ba]          = fg ? (float)lab : (float)C;     // labels
    out[N * 85 + ba] = fg ? 1.0f : 0.0f;               // fg
    out[N * 86 + ba] = fg ? (float)mg : 0.0f;          // tgt_idx
    ((float4*)(out + N))[ba] = boxv;                   // tboxes
    if (fg)                                            // tscores scatter
        out[N * 5 + ba * 80 + lab] = piou;
}

// ---------------------------------------------------------------------------
extern "C" void kernel_launch(void* const* d_in, const int* in_sizes, int n_in,
                              void* d_out, int out_size)
{
    const float* scores = (const float*)d_in[0];   // (16, 33600, 80)
    const float* pboxes = (const float*)d_in[1];   // (16, 33600, 4)
    const float* anc    = (const float*)d_in[2];   // (33600, 2)
    const int*   glab   = (const int*)  d_in[3];   // (16, 64, 1)
    const float* gbox   = (const float*)d_in[4];   // (16, 64, 4)
    const int*   gmask  = (const int*)  d_in[5];   // (16, 64, 1)
    const float* strd   = (const float*)d_in[6];   // (16, 33600, 1)
    float* out = (float*)d_out;
    float* ts  = out + (size_t)BS * A * 5;         // tscores region

    kz<<<1, 1024>>>();
    dim3 gg(NCHUNK, BS);
    k1a<<<gg, TILE>>>(pboxes, anc, gbox, gmask, strd, ts);
    k1b<<<gg, TILE>>>(scores, glab, gbox, gmask, ts);
    k2<<<BS * G, 256>>>(scores, pboxes, glab, gbox, gmask, ts);
    k3<<<gg, TILE>>>(pboxes, glab, gbox, gmask, out);
}